// round 14
// baseline (speedup 1.0000x reference)
#include <cuda_runtime.h>

#define CFRAME 384
#define NAA    21
#define NRES   2048
#define NRIG   8192
#define BATCH  16
#define THREADS 128                     // 4 warps per block
#define RIGID_BLOCKS 356
#define RES_BLOCKS   88
#define NBLOCKS (RIGID_BLOCKS + RES_BLOCKS)    // 444 = 3/SM
#define RIGID_WARPS (RIGID_BLOCKS*4)    // 1424
#define RES_WARPS   (RES_BLOCKS*4)      // 352
#define TILE_ROWS 64
#define RIGID_TILES ((BATCH*NRIG)/TILE_ROWS)   // 2048
#define RES_TILES   ((BATCH*NRES)/TILE_ROWS)   // 512
#define WTAB   (CFRAME*6)               // float4 per weight table (2304)
#define CH9    9                        // stage row stride in float4 (8 used + 1 pad)
#define STAGE_F4 (TILE_ROWS*CH9)        // 576 float4 per warp
#define SMEM_F4 (WTAB + 4*STAGE_F4)     // 4608 float4 (ONE table + staging)
#define SMEM_BYTES (SMEM_F4*16)         // 73728 -> 3 blocks/SM
#define OUT_F4 ((BATCH*NRES*NAA)/4)     // 172032 float4 (exact)

typedef unsigned long long u64;

// ---------------- device scratch (no allocations) ---------------------------
__device__ float4 g_Wg[WTAB];    // rigid: g-folded Wc; [c*6+5] = (g*wc20, 1, 0, 0)
__device__ float4 g_Wo[WTAB];    // res:   W_out;       [c*6+5] = (w20, 0, 0, 0)
__device__ float2 g_A2[11];
__device__ float2 g_B2[11];
__device__ float2 g_Bo2[11];
__device__ float  g_Wc8[8*CFRAME*NAA];  // 8 s-partials of Wc, layout [cj*8 + q]
__device__ int    g_idx64;

// ---- packed f32x2 helpers ----
__device__ __forceinline__ u64 pk2(float lo, float hi){u64 r;asm("mov.b64 %0,{%1,%2};":"=l"(r):"f"(lo),"f"(hi));return r;}
__device__ __forceinline__ u64 dup2(float v){return pk2(v,v);}
__device__ __forceinline__ void upk2(u64 v,float&lo,float&hi){asm("mov.b64 {%0,%1},%2;":"=f"(lo),"=f"(hi):"l"(v));}
__device__ __forceinline__ u64 fma2(u64 a,u64 b,u64 c){u64 d;asm("fma.rn.f32x2 %0,%1,%2,%3;":"=l"(d):"l"(a),"l"(b),"l"(c));return d;}
__device__ __forceinline__ u64 mul2(u64 a,u64 b){u64 d;asm("mul.rn.f32x2 %0,%1,%2;":"=l"(d):"l"(a),"l"(b));return d;}

// ---------------------------------------------------------------------------
// prep1 (R11 fast form): 8-way s-split partials, W_out staged in SMEM.
// t = cj*8 + q; partial over s in [q*48, (q+1)*48).
// ---------------------------------------------------------------------------
__global__ void prep1(const float* __restrict__ W_su, const float* __restrict__ W_out){
    __shared__ float Ws[CFRAME*NAA];
    for (int i = threadIdx.x; i < CFRAME*NAA; i += blockDim.x) Ws[i] = W_out[i];
    __syncthreads();
    int t = blockIdx.x*blockDim.x + threadIdx.x;
    if (t >= 8*CFRAME*NAA) return;
    int q  = t & 7, cj = t >> 3;
    int c = cj / NAA, j = cj - c*NAA;
    const float* wr = W_su + (size_t)c*CFRAME + q*48;
    const float* wo = Ws + (size_t)(q*48)*NAA + j;
    float a0=0.f, a1=0.f, a2=0.f, a3=0.f;
    #pragma unroll
    for (int s = 0; s < 48; s += 4){
        a0 = fmaf(wr[s+0], wo[(s+0)*NAA], a0);
        a1 = fmaf(wr[s+1], wo[(s+1)*NAA], a1);
        a2 = fmaf(wr[s+2], wo[(s+2)*NAA], a2);
        a3 = fmaf(wr[s+3], wo[(s+3)*NAA], a3);
    }
    g_Wc8[t] = (a0+a1) + (a2+a3);
}

// sum the 8 adjacent partials for (c,j): two coalesced float4 loads
__device__ __forceinline__ float wc_of(int c, int j){
    const float4* p = (const float4*)(g_Wc8 + (size_t)(c*NAA + j)*8);
    float4 a = p[0], b = p[1];
    return ((a.x+a.y)+(a.z+a.w)) + ((b.x+b.y)+(b.z+b.w));
}

// ---------------------------------------------------------------------------
// prep2: blocks 0-1 build tables + epilogue vectors + parallel idx probe
// (consuming g_Wc8 partials directly); blocks >= 2 zero the output buffer.
// ---------------------------------------------------------------------------
__global__ void prep2(const float* __restrict__ ln_g, const float* __restrict__ ln_b,
                      const float* __restrict__ b_su, const float* __restrict__ W_out,
                      const float* __restrict__ b_out, const void* __restrict__ idx_ptr,
                      float4* __restrict__ outz){
    if (blockIdx.x >= 2){
        int i = (blockIdx.x - 2)*blockDim.x + threadIdx.x;
        if (i < OUT_F4) outz[i] = make_float4(0.f, 0.f, 0.f, 0.f);
        return;
    }
    int t = blockIdx.x*blockDim.x + threadIdx.x;
    if (t < CFRAME){
        int c = t;
        float g = ln_g[c];
        float wc[NAA];
        #pragma unroll
        for (int j = 0; j < NAA; j++) wc[j] = wc_of(c, j);
        const float* wo = W_out + c*NAA;
        #pragma unroll
        for (int k = 0; k < 5; k++){
            g_Wg[c*6+k] = make_float4(g*wc[4*k], g*wc[4*k+1], g*wc[4*k+2], g*wc[4*k+3]);
            g_Wo[c*6+k] = make_float4(wo[4*k], wo[4*k+1], wo[4*k+2], wo[4*k+3]);
        }
        g_Wg[c*6+5] = make_float4(g*wc[20], 1.0f, 0.f, 0.f);   // ones col -> sum(x)
        g_Wo[c*6+5] = make_float4(wo[20],   0.0f, 0.f, 0.f);
    } else if (t < CFRAME + NAA){
        int j = t - CFRAME;
        float A0=0.f,A1=0.f,A2v=0.f,A3=0.f, B0=0.f,B1=0.f,B2v=0.f,B3=0.f;
        for (int c = 0; c < CFRAME; c += 4){
            float w0 = wc_of(c+0, j);
            float w1 = wc_of(c+1, j);
            float w2 = wc_of(c+2, j);
            float w3 = wc_of(c+3, j);
            A0 = fmaf(ln_g[c+0], w0, A0);  B0 = fmaf(ln_b[c+0], w0, B0);
            A1 = fmaf(ln_g[c+1], w1, A1);  B1 = fmaf(ln_b[c+1], w1, B1);
            A2v= fmaf(ln_g[c+2], w2, A2v); B2v= fmaf(ln_b[c+2], w2, B2v);
            A3 = fmaf(ln_g[c+3], w3, A3);  B3 = fmaf(ln_b[c+3], w3, B3);
        }
        float Bv = (B0+B1)+(B2v+B3);
        float b0=0.f,b1=0.f,b2=0.f,b3=0.f;
        for (int s = 0; s < CFRAME; s += 4){
            b0 = fmaf(b_su[s+0], W_out[(s+0)*NAA+j], b0);
            b1 = fmaf(b_su[s+1], W_out[(s+1)*NAA+j], b1);
            b2 = fmaf(b_su[s+2], W_out[(s+2)*NAA+j], b2);
            b3 = fmaf(b_su[s+3], W_out[(s+3)*NAA+j], b3);
        }
        Bv += (b0+b1)+(b2+b3);
        ((float*)g_A2)[j]  = (A0+A1)+(A2v+A3);
        ((float*)g_B2)[j]  = Bv;
        ((float*)g_Bo2)[j] = b_out[j];
        if (j == 20){ ((float*)g_A2)[21]=0.f; ((float*)g_B2)[21]=0.f; ((float*)g_Bo2)[21]=0.f; }
    } else if (t >= 416 && t < 448){
        // parallel idx dtype probe
        int lane = t - 416;
        const long long* p = (const long long*)idx_ptr;
        long long v0 = p[lane], v1 = p[lane + 32];
        bool ok = (v0 >= 0 && v0 < NRES) && (v1 >= 0 && v1 < NRES);
        unsigned b = __ballot_sync(0xffffffffu, ok);
        if (lane == 0) g_idx64 = (b == 0xffffffffu) ? 1 : 0;
    }
}

// ---------------------------------------------------------------------------
// per-row epilogues
// ---------------------------------------------------------------------------
__device__ __forceinline__ void epi_res(const u64 acc[11], float* __restrict__ out, int row){
    float* dst = out + (size_t)row*NAA;
    #pragma unroll
    for (int q = 0; q < 10; q++){
        float2 bo = g_Bo2[q];
        float o0, o1; upk2(acc[q], o0, o1);
        atomicAdd(dst + 2*q,     o0 + bo.x);
        atomicAdd(dst + 2*q + 1, o1 + bo.y);
    }
    float accS, dumm; upk2(acc[10], accS, dumm);
    atomicAdd(dst + 20, accS + g_Bo2[10].x);
}

__device__ __forceinline__ void epi_rigid(const u64 acc[11], float s2,
                                          const void* __restrict__ idxp,
                                          const float* __restrict__ mask,
                                          float* __restrict__ out, int row, int use64){
    float accS, s; upk2(acc[10], accS, s);
    const float mu = s * (1.f/CFRAME);
    const float rs = rsqrtf(fmaf(s2, 1.f/CFRAME, -mu*mu) + 1e-5f);
    const float m  = mask[row];
    const int iv = use64 ? (int)((const long long*)idxp)[row]
                         : ((const int*)idxp)[row];
    if (m != 0.f){
        float* dst = out + ((size_t)(row >> 13)*NRES + (size_t)iv)*NAA;
        const float rm = rs*m;
        const u64 rmd = dup2(rm), md = dup2(m), nmud = dup2(-mu);
        #pragma unroll
        for (int q = 0; q < 10; q++){
            float2 a = g_A2[q], b = g_B2[q];
            u64 o = fma2(nmud, pk2(a.x,a.y), acc[q]);      // acc - mu*A
            o     = fma2(rmd, o, mul2(md, pk2(b.x,b.y)));  // rs*m*(..) + m*B
            float o0, o1; upk2(o, o0, o1);
            atomicAdd(dst + 2*q,     o0);
            atomicAdd(dst + 2*q + 1, o1);
        }
        float oS = rm*(accS - mu*g_A2[10].x) + m*g_B2[10].x;
        atomicAdd(dst + 20, oS);
    }
}

// ---------------------------------------------------------------------------
// tile engine (R9 / best measured — UNCHANGED): 64-row tile, lane owns rows
// (lane, lane+32); 12 chunks x 32 channels; CH9 staging.
// ---------------------------------------------------------------------------
template<bool RES>
__device__ __forceinline__ void do_tile(int row0, const float* __restrict__ xbase,
                                        const float4* __restrict__ W,
                                        const void* __restrict__ idxp,
                                        const float* __restrict__ mask,
                                        float* __restrict__ out,
                                        float4* __restrict__ xs, int lane, int use64){
    u64 accA[11], accB[11];
    #pragma unroll
    for (int q = 0; q < 11; q++){ accA[q] = 0ull; accB[q] = 0ull; }
    float s2A = 0.f, s2B = 0.f;

    const int qld = lane & 7, sub = lane >> 3;

    for (int cb = 0; cb < 12; cb++){
        #pragma unroll
        for (int r = 0; r < 16; r++){
            int row = r*4 + sub;
            xs[row*CH9 + qld] =
                *(const float4*)(xbase + (size_t)(row0+row)*CFRAME + cb*32 + qld*4);
        }
        __syncwarp();
        #pragma unroll 2
        for (int i = 0; i < 8; i++){
            float4 xa = xs[lane*CH9 + i];
            float4 xb = xs[(lane+32)*CH9 + i];
            const float fa4[4] = {xa.x, xa.y, xa.z, xa.w};
            const float fb4[4] = {xb.x, xb.y, xb.z, xb.w};
            #pragma unroll
            for (int u = 0; u < 4; u++){
                const int c = cb*32 + i*4 + u;
                const float fa = fa4[u], fb = fb4[u];
                if (!RES){ s2A = fmaf(fa, fa, s2A); s2B = fmaf(fb, fb, s2B); }
                const u64 da = dup2(fa), db = dup2(fb);
                const float4* wc = W + c*6;
                float4 w0 = wc[0], w1 = wc[1], w2 = wc[2], w3 = wc[3], w4 = wc[4];
                float2 w5 = *(const float2*)(wc + 5);
                u64 p0 = pk2(w0.x,w0.y), p1 = pk2(w0.z,w0.w);
                u64 p2 = pk2(w1.x,w1.y), p3 = pk2(w1.z,w1.w);
                u64 p4 = pk2(w2.x,w2.y), p5 = pk2(w2.z,w2.w);
                u64 p6 = pk2(w3.x,w3.y), p7 = pk2(w3.z,w3.w);
                u64 p8 = pk2(w4.x,w4.y), p9 = pk2(w4.z,w4.w);
                u64 p10= pk2(w5.x,w5.y);
                accA[0] = fma2(da, p0, accA[0]);  accB[0] = fma2(db, p0, accB[0]);
                accA[1] = fma2(da, p1, accA[1]);  accB[1] = fma2(db, p1, accB[1]);
                accA[2] = fma2(da, p2, accA[2]);  accB[2] = fma2(db, p2, accB[2]);
                accA[3] = fma2(da, p3, accA[3]);  accB[3] = fma2(db, p3, accB[3]);
                accA[4] = fma2(da, p4, accA[4]);  accB[4] = fma2(db, p4, accB[4]);
                accA[5] = fma2(da, p5, accA[5]);  accB[5] = fma2(db, p5, accB[5]);
                accA[6] = fma2(da, p6, accA[6]);  accB[6] = fma2(db, p6, accB[6]);
                accA[7] = fma2(da, p7, accA[7]);  accB[7] = fma2(db, p7, accB[7]);
                accA[8] = fma2(da, p8, accA[8]);  accB[8] = fma2(db, p8, accB[8]);
                accA[9] = fma2(da, p9, accA[9]);  accB[9] = fma2(db, p9, accB[9]);
                accA[10]= fma2(da, p10, accA[10]);accB[10]= fma2(db, p10, accB[10]);
            }
        }
        __syncwarp();
    }

    if (RES){
        epi_res(accA, out, row0 + lane);
        epi_res(accB, out, row0 + lane + 32);
    } else {
        epi_rigid(accA, s2A, idxp, mask, out, row0 + lane,      use64);
        epi_rigid(accB, s2B, idxp, mask, out, row0 + lane + 32, use64);
    }
}

// ---------------------------------------------------------------------------
// fused kernel (R13 — typed blocks, 3 blocks/SM): one table in SMEM,
// static grid-stride per type. Engine untouched.
// ---------------------------------------------------------------------------
__global__ void __launch_bounds__(THREADS,3)
fused_kernel(const float* __restrict__ x, const void* __restrict__ idxp,
             const float* __restrict__ mask, const float* __restrict__ seqo,
             float* __restrict__ out){
    extern __shared__ float4 sm4[];
    const int lane = threadIdx.x & 31;
    const int w    = threadIdx.x >> 5;
    float4* xs = sm4 + WTAB + w*STAGE_F4;
    const bool isRes = (blockIdx.x >= RIGID_BLOCKS);

    {
        const float4* src = isRes ? g_Wo : g_Wg;
        for (int i = threadIdx.x; i < WTAB; i += THREADS) sm4[i] = src[i];
    }
    __syncthreads();
    const int use64 = g_idx64;

    if (isRes){
        const int gw = (blockIdx.x - RIGID_BLOCKS)*4 + w;
        for (int t = gw; t < RES_TILES; t += RES_WARPS)
            do_tile<true>(t*TILE_ROWS, seqo, sm4, idxp, mask, out, xs, lane, use64);
    } else {
        const int gw = blockIdx.x*4 + w;
        for (int t = gw; t < RIGID_TILES; t += RIGID_WARPS)
            do_tile<false>(t*TILE_ROWS, x, sm4, idxp, mask, out, xs, lane, use64);
    }
}

// ---------------------------------------------------------------------------
extern "C" void kernel_launch(void* const* d_in, const int* in_sizes, int n_in,
                              void* d_out, int out_size) {
    const float* x     = (const float*)d_in[0];  // rigids_embed_flat [16,8192,384]
    const void*  idxp  = d_in[1];                // rigids_to_res_idx [16,8192]
    const float* mask  = (const float*)d_in[2];  // rigids_mask [16,8192]
    const float* seqo  = (const float*)d_in[3];  // out [16,2048,384]
    const float* ln_g  = (const float*)d_in[4];
    const float* ln_b  = (const float*)d_in[5];
    const float* W_su  = (const float*)d_in[6];  // [384,384]
    const float* b_su  = (const float*)d_in[7];  // [384]
    const float* W_out = (const float*)d_in[8];  // [384,21]
    const float* b_out = (const float*)d_in[9];  // [21]
    float* out = (float*)d_out;                  // [16,2048,21]

    cudaFuncSetAttribute(fused_kernel,
                         cudaFuncAttributeMaxDynamicSharedMemorySize, SMEM_BYTES);

    prep1<<<(8*CFRAME*NAA + 255)/256, 256>>>(W_su, W_out);
    prep2<<<2 + (OUT_F4 + 255)/256, 256>>>(ln_g, ln_b, b_su, W_out, b_out, idxp,
                                           (float4*)out);
    fused_kernel<<<NBLOCKS, THREADS, SMEM_BYTES>>>(x, idxp, mask, seqo, out);
}

// round 15
// speedup vs baseline: 1.5151x; 1.5151x over previous
#include <cuda_runtime.h>

#define CFRAME 384
#define NAA    21
#define NRES   2048
#define NRIG   8192
#define BATCH  16
#define THREADS 128                     // 4 warps per block
#define NBLOCKS 296                     // 2 blocks/SM (smem-capped)
#define WARPS_TOTAL (NBLOCKS*4)         // 1184
#define TILE_ROWS 64
#define RIGID_TILES ((BATCH*NRIG)/TILE_ROWS)   // 2048
#define RES_TILES   ((BATCH*NRES)/TILE_ROWS)   // 512
#define NTILES (RIGID_TILES + RES_TILES)       // 2560
#define WTAB   (CFRAME*6)               // float4 per weight table (2304)
#define CH9    9                        // stage row stride in float4 (8 used + 1 pad)
#define STAGE_F4 (TILE_ROWS*CH9)        // 576 float4 per warp
#define SMEM_F4 (2*WTAB + 4*STAGE_F4)   // 6912 float4
#define SMEM_BYTES (SMEM_F4*16)         // 110592
#define OUT_F4 ((BATCH*NRES*NAA)/4)     // 172032 float4 (exact)

typedef unsigned long long u64;

// ---------------- device scratch (no allocations) ---------------------------
__device__ float4 g_Wg[WTAB];    // rigid: g-folded Wc; [c*6+5] = (g*wc20, 1, 0, 0)
__device__ float4 g_Wo[WTAB];    // res:   W_out;       [c*6+5] = (w20, 0, 0, 0)
__device__ float2 g_A2[11];
__device__ float2 g_B2[11];
__device__ float2 g_Bo2[11];
__device__ float  g_Wc8[8*CFRAME*NAA];  // 8 s-partials of Wc, layout [cj*8 + q]
__device__ float  g_Wc[CFRAME*NAA];
__device__ int    g_idx64;

// ---- packed f32x2 helpers ----
__device__ __forceinline__ u64 pk2(float lo, float hi){u64 r;asm("mov.b64 %0,{%1,%2};":"=l"(r):"f"(lo),"f"(hi));return r;}
__device__ __forceinline__ u64 dup2(float v){return pk2(v,v);}
__device__ __forceinline__ void upk2(u64 v,float&lo,float&hi){asm("mov.b64 {%0,%1},%2;":"=f"(lo),"=f"(hi):"l"(v));}
__device__ __forceinline__ u64 fma2(u64 a,u64 b,u64 c){u64 d;asm("fma.rn.f32x2 %0,%1,%2,%3;":"=l"(d):"l"(a),"l"(b),"l"(c));return d;}
__device__ __forceinline__ u64 mul2(u64 a,u64 b){u64 d;asm("mul.rn.f32x2 %0,%1,%2;":"=l"(d):"l"(a),"l"(b));return d;}

// ---------------------------------------------------------------------------
// prep1: 8-way s-split partials, W_out staged in SMEM. t = cj*8 + q.
// ---------------------------------------------------------------------------
__global__ void prep1(const float* __restrict__ W_su, const float* __restrict__ W_out){
    __shared__ float Ws[CFRAME*NAA];
    for (int i = threadIdx.x; i < CFRAME*NAA; i += blockDim.x) Ws[i] = W_out[i];
    __syncthreads();
    int t = blockIdx.x*blockDim.x + threadIdx.x;
    if (t >= 8*CFRAME*NAA) return;
    int q  = t & 7, cj = t >> 3;
    int c = cj / NAA, j = cj - c*NAA;
    const float* wr = W_su + (size_t)c*CFRAME + q*48;
    const float* wo = Ws + (size_t)(q*48)*NAA + j;
    float a0=0.f, a1=0.f, a2=0.f, a3=0.f;
    #pragma unroll
    for (int s = 0; s < 48; s += 4){
        a0 = fmaf(wr[s+0], wo[(s+0)*NAA], a0);
        a1 = fmaf(wr[s+1], wo[(s+1)*NAA], a1);
        a2 = fmaf(wr[s+2], wo[(s+2)*NAA], a2);
        a3 = fmaf(wr[s+3], wo[(s+3)*NAA], a3);
    }
    g_Wc8[t] = (a0+a1) + (a2+a3);
}

// prep1b: reduce 8 adjacent partials -> g_Wc (two coalesced float4 loads)
__global__ void prep1b(){
    int t = blockIdx.x*blockDim.x + threadIdx.x;
    if (t >= CFRAME*NAA) return;
    float4 a = ((const float4*)g_Wc8)[t*2];
    float4 b = ((const float4*)g_Wc8)[t*2+1];
    g_Wc[t] = ((a.x+a.y)+(a.z+a.w)) + ((b.x+b.y)+(b.z+b.w));
}

// ---------------------------------------------------------------------------
// prep2: blocks 0-1 build tables (read g_Wc); block 2 computes A/B vectors
// in parallel (168 threads) + parallel idx probe; blocks >= 3 zero out.
// ---------------------------------------------------------------------------
__global__ void prep2(const float* __restrict__ ln_g, const float* __restrict__ ln_b,
                      const float* __restrict__ b_su, const float* __restrict__ W_out,
                      const float* __restrict__ b_out, const void* __restrict__ idx_ptr,
                      float4* __restrict__ outz){
    if (blockIdx.x >= 3){
        int i = (blockIdx.x - 3)*blockDim.x + threadIdx.x;
        if (i < OUT_F4) outz[i] = make_float4(0.f, 0.f, 0.f, 0.f);
        return;
    }
    if (blockIdx.x < 2){
        int c = blockIdx.x*blockDim.x + threadIdx.x;   // 0..511, active < 384
        if (c < CFRAME){
            float g = ln_g[c];
            const float* wc = g_Wc + c*NAA;
            const float* wo = W_out + c*NAA;
            #pragma unroll
            for (int k = 0; k < 5; k++){
                g_Wg[c*6+k] = make_float4(g*wc[4*k], g*wc[4*k+1], g*wc[4*k+2], g*wc[4*k+3]);
                g_Wo[c*6+k] = make_float4(wo[4*k], wo[4*k+1], wo[4*k+2], wo[4*k+3]);
            }
            g_Wg[c*6+5] = make_float4(g*wc[20], 1.0f, 0.f, 0.f);   // ones col -> sum(x)
            g_Wo[c*6+5] = make_float4(wo[20],   0.0f, 0.f, 0.f);
        }
        return;
    }
    // block 2: parallel A/B vectors + probe
    __shared__ float sA[NAA][8], sB[NAA][8];
    const int tid = threadIdx.x;
    if (tid < NAA*8){
        const int j  = tid >> 3;
        const int ch = tid & 7;
        const int s0 = ch*48;
        float A0=0.f,A1=0.f, B0=0.f,B1=0.f, C0=0.f,C1=0.f;
        #pragma unroll 4
        for (int s = s0; s < s0+48; s += 2){
            float w0 = g_Wc[(s+0)*NAA + j];
            float w1 = g_Wc[(s+1)*NAA + j];
            A0 = fmaf(ln_g[s+0], w0, A0);  A1 = fmaf(ln_g[s+1], w1, A1);
            B0 = fmaf(ln_b[s+0], w0, B0);  B1 = fmaf(ln_b[s+1], w1, B1);
            C0 = fmaf(b_su[s+0], W_out[(s+0)*NAA+j], C0);
            C1 = fmaf(b_su[s+1], W_out[(s+1)*NAA+j], C1);
        }
        sA[j][ch] = A0 + A1;
        sB[j][ch] = (B0 + B1) + (C0 + C1);
    }
    __syncthreads();
    if (tid < NAA){
        int j = tid;
        float A = 0.f, Bv = 0.f;
        #pragma unroll
        for (int ch = 0; ch < 8; ch++){ A += sA[j][ch]; Bv += sB[j][ch]; }
        ((float*)g_A2)[j]  = A;
        ((float*)g_B2)[j]  = Bv;
        ((float*)g_Bo2)[j] = b_out[j];
        if (j == 20){ ((float*)g_A2)[21]=0.f; ((float*)g_B2)[21]=0.f; ((float*)g_Bo2)[21]=0.f; }
    } else if (tid >= 192 && tid < 224){
        // parallel idx dtype probe on a clean full warp
        int lane = tid - 192;
        const long long* p = (const long long*)idx_ptr;
        long long v0 = p[lane], v1 = p[lane + 32];
        bool ok = (v0 >= 0 && v0 < NRES) && (v1 >= 0 && v1 < NRES);
        unsigned b = __ballot_sync(0xffffffffu, ok);
        if (lane == 0) g_idx64 = (b == 0xffffffffu) ? 1 : 0;
    }
}

// ---------------------------------------------------------------------------
// per-row epilogues
// ---------------------------------------------------------------------------
__device__ __forceinline__ void epi_res(const u64 acc[11], float* __restrict__ out, int row){
    float* dst = out + (size_t)row*NAA;
    #pragma unroll
    for (int q = 0; q < 10; q++){
        float2 bo = g_Bo2[q];
        float o0, o1; upk2(acc[q], o0, o1);
        atomicAdd(dst + 2*q,     o0 + bo.x);
        atomicAdd(dst + 2*q + 1, o1 + bo.y);
    }
    float accS, dumm; upk2(acc[10], accS, dumm);
    atomicAdd(dst + 20, accS + g_Bo2[10].x);
}

__device__ __forceinline__ void epi_rigid(const u64 acc[11], float s2,
                                          const void* __restrict__ idxp,
                                          const float* __restrict__ mask,
                                          float* __restrict__ out, int row, int use64){
    float accS, s; upk2(acc[10], accS, s);
    const float mu = s * (1.f/CFRAME);
    const float rs = rsqrtf(fmaf(s2, 1.f/CFRAME, -mu*mu) + 1e-5f);
    const float m  = mask[row];
    const int iv = use64 ? (int)((const long long*)idxp)[row]
                         : ((const int*)idxp)[row];
    if (m != 0.f){
        float* dst = out + ((size_t)(row >> 13)*NRES + (size_t)iv)*NAA;
        const float rm = rs*m;
        const u64 rmd = dup2(rm), md = dup2(m), nmud = dup2(-mu);
        #pragma unroll
        for (int q = 0; q < 10; q++){
            float2 a = g_A2[q], b = g_B2[q];
            u64 o = fma2(nmud, pk2(a.x,a.y), acc[q]);      // acc - mu*A
            o     = fma2(rmd, o, mul2(md, pk2(b.x,b.y)));  // rs*m*(..) + m*B
            float o0, o1; upk2(o, o0, o1);
            atomicAdd(dst + 2*q,     o0);
            atomicAdd(dst + 2*q + 1, o1);
        }
        float oS = rm*(accS - mu*g_A2[10].x) + m*g_B2[10].x;
        atomicAdd(dst + 20, oS);
    }
}

// ---------------------------------------------------------------------------
// tile engine (R9/R11 — best measured, UNCHANGED): 64-row tile, lane owns rows
// (lane, lane+32); 12 chunks x 32 channels; CH9 staging.
// ---------------------------------------------------------------------------
template<bool RES>
__device__ __forceinline__ void do_tile(int row0, const float* __restrict__ xbase,
                                        const float4* __restrict__ W,
                                        const void* __restrict__ idxp,
                                        const float* __restrict__ mask,
                                        float* __restrict__ out,
                                        float4* __restrict__ xs, int lane, int use64){
    u64 accA[11], accB[11];
    #pragma unroll
    for (int q = 0; q < 11; q++){ accA[q] = 0ull; accB[q] = 0ull; }
    float s2A = 0.f, s2B = 0.f;

    const int qld = lane & 7, sub = lane >> 3;

    for (int cb = 0; cb < 12; cb++){
        #pragma unroll
        for (int r = 0; r < 16; r++){
            int row = r*4 + sub;
            xs[row*CH9 + qld] =
                *(const float4*)(xbase + (size_t)(row0+row)*CFRAME + cb*32 + qld*4);
        }
        __syncwarp();
        #pragma unroll 2
        for (int i = 0; i < 8; i++){
            float4 xa = xs[lane*CH9 + i];
            float4 xb = xs[(lane+32)*CH9 + i];
            const float fa4[4] = {xa.x, xa.y, xa.z, xa.w};
            const float fb4[4] = {xb.x, xb.y, xb.z, xb.w};
            #pragma unroll
            for (int u = 0; u < 4; u++){
                const int c = cb*32 + i*4 + u;
                const float fa = fa4[u], fb = fb4[u];
                if (!RES){ s2A = fmaf(fa, fa, s2A); s2B = fmaf(fb, fb, s2B); }
                const u64 da = dup2(fa), db = dup2(fb);
                const float4* wc = W + c*6;
                float4 w0 = wc[0], w1 = wc[1], w2 = wc[2], w3 = wc[3], w4 = wc[4];
                float2 w5 = *(const float2*)(wc + 5);
                u64 p0 = pk2(w0.x,w0.y), p1 = pk2(w0.z,w0.w);
                u64 p2 = pk2(w1.x,w1.y), p3 = pk2(w1.z,w1.w);
                u64 p4 = pk2(w2.x,w2.y), p5 = pk2(w2.z,w2.w);
                u64 p6 = pk2(w3.x,w3.y), p7 = pk2(w3.z,w3.w);
                u64 p8 = pk2(w4.x,w4.y), p9 = pk2(w4.z,w4.w);
                u64 p10= pk2(w5.x,w5.y);
                accA[0] = fma2(da, p0, accA[0]);  accB[0] = fma2(db, p0, accB[0]);
                accA[1] = fma2(da, p1, accA[1]);  accB[1] = fma2(db, p1, accB[1]);
                accA[2] = fma2(da, p2, accA[2]);  accB[2] = fma2(db, p2, accB[2]);
                accA[3] = fma2(da, p3, accA[3]);  accB[3] = fma2(db, p3, accB[3]);
                accA[4] = fma2(da, p4, accA[4]);  accB[4] = fma2(db, p4, accB[4]);
                accA[5] = fma2(da, p5, accA[5]);  accB[5] = fma2(db, p5, accB[5]);
                accA[6] = fma2(da, p6, accA[6]);  accB[6] = fma2(db, p6, accB[6]);
                accA[7] = fma2(da, p7, accA[7]);  accB[7] = fma2(db, p7, accB[7]);
                accA[8] = fma2(da, p8, accA[8]);  accB[8] = fma2(db, p8, accB[8]);
                accA[9] = fma2(da, p9, accA[9]);  accB[9] = fma2(db, p9, accB[9]);
                accA[10]= fma2(da, p10, accA[10]);accB[10]= fma2(db, p10, accB[10]);
            }
        }
        __syncwarp();
    }

    if (RES){
        epi_res(accA, out, row0 + lane);
        epi_res(accB, out, row0 + lane + 32);
    } else {
        epi_rigid(accA, s2A, idxp, mask, out, row0 + lane,      use64);
        epi_rigid(accB, s2B, idxp, mask, out, row0 + lane + 32, use64);
    }
}

// ---------------------------------------------------------------------------
// fused kernel (R9/R11 — best measured, UNCHANGED): unified tile space,
// static grid-stride; both weight tables resident in SMEM.
// ---------------------------------------------------------------------------
__global__ void __launch_bounds__(THREADS,2)
fused_kernel(const float* __restrict__ x, const void* __restrict__ idxp,
             const float* __restrict__ mask, const float* __restrict__ seqo,
             float* __restrict__ out){
    extern __shared__ float4 sm4[];
    float4* Wg = sm4;                 // WTAB
    float4* Wo = sm4 + WTAB;          // WTAB
    const int lane = threadIdx.x & 31;
    const int w    = threadIdx.x >> 5;
    float4* xs = sm4 + 2*WTAB + w*STAGE_F4;

    for (int i = threadIdx.x; i < WTAB; i += THREADS){
        Wg[i] = g_Wg[i];
        Wo[i] = g_Wo[i];
    }
    __syncthreads();
    const int use64 = g_idx64;

    const int gw = blockIdx.x*4 + w;
    for (int t = gw; t < NTILES; t += WARPS_TOTAL){
        if (t < RIGID_TILES)
            do_tile<false>(t*TILE_ROWS, x, Wg, idxp, mask, out, xs, lane, use64);
        else
            do_tile<true>((t-RIGID_TILES)*TILE_ROWS, seqo, Wo, idxp, mask, out, xs, lane, use64);
    }
}

// ---------------------------------------------------------------------------
extern "C" void kernel_launch(void* const* d_in, const int* in_sizes, int n_in,
                              void* d_out, int out_size) {
    const float* x     = (const float*)d_in[0];  // rigids_embed_flat [16,8192,384]
    const void*  idxp  = d_in[1];                // rigids_to_res_idx [16,8192]
    const float* mask  = (const float*)d_in[2];  // rigids_mask [16,8192]
    const float* seqo  = (const float*)d_in[3];  // out [16,2048,384]
    const float* ln_g  = (const float*)d_in[4];
    const float* ln_b  = (const float*)d_in[5];
    const float* W_su  = (const float*)d_in[6];  // [384,384]
    const float* b_su  = (const float*)d_in[7];  // [384]
    const float* W_out = (const float*)d_in[8];  // [384,21]
    const float* b_out = (const float*)d_in[9];  // [21]
    float* out = (float*)d_out;                  // [16,2048,21]

    cudaFuncSetAttribute(fused_kernel,
                         cudaFuncAttributeMaxDynamicSharedMemorySize, SMEM_BYTES);

    prep1<<<(8*CFRAME*NAA + 255)/256, 256>>>(W_su, W_out);
    prep1b<<<(CFRAME*NAA + 255)/256, 256>>>();
    prep2<<<3 + (OUT_F4 + 255)/256, 256>>>(ln_g, ln_b, b_su, W_out, b_out, idxp,
                                           (float4*)out);
    fused_kernel<<<NBLOCKS, THREADS, SMEM_BYTES>>>(x, idxp, mask, seqo, out);
}

// round 16
// speedup vs baseline: 1.5394x; 1.0161x over previous
#include <cuda_runtime.h>

#define CFRAME 384
#define NAA    21
#define NRES   2048
#define NRIG   8192
#define BATCH  16
#define THREADS 128                     // 4 warps per block
#define NBLOCKS 296                     // 2 blocks/SM (smem-capped)
#define WARPS_TOTAL (NBLOCKS*4)         // 1184
#define TILE_ROWS 64
#define RIGID_TILES ((BATCH*NRIG)/TILE_ROWS)   // 2048
#define RES_TILES   ((BATCH*NRES)/TILE_ROWS)   // 512
#define NTILES (RIGID_TILES + RES_TILES)       // 2560
#define WTAB   (CFRAME*6)               // float4 per weight table (2304)
#define CH9    9                        // stage row stride in float4 (8 used + 1 pad)
#define STAGE_F4 (TILE_ROWS*CH9)        // 576 float4 per warp
#define SMEM_F4 (2*WTAB + 4*STAGE_F4)   // 6912 float4
#define SMEM_BYTES (SMEM_F4*16)         // 110592
#define OUT_F4 ((BATCH*NRES*NAA)/4)     // 172032 float4 (exact)

typedef unsigned long long u64;

// ---------------- device scratch (no allocations) ---------------------------
__device__ float4 g_Wg[WTAB];    // rigid: g-folded Wc; [c*6+5] = (g*wc20, 1, 0, 0)
__device__ float4 g_Wo[WTAB];    // res:   W_out;       [c*6+5] = (w20, 0, 0, 0)
__device__ float2 g_A2[11];
__device__ float2 g_B2[11];
__device__ float2 g_Bo2[11];
__device__ float  g_Wc8[8*CFRAME*NAA];  // 8 s-partials of Wc, PAIR layout [cj*8 + q]
__device__ int    g_idx64;

// ---- packed f32x2 helpers ----
__device__ __forceinline__ u64 pk2(float lo, float hi){u64 r;asm("mov.b64 %0,{%1,%2};":"=l"(r):"f"(lo),"f"(hi));return r;}
__device__ __forceinline__ u64 dup2(float v){return pk2(v,v);}
__device__ __forceinline__ void upk2(u64 v,float&lo,float&hi){asm("mov.b64 {%0,%1},%2;":"=f"(lo),"=f"(hi):"l"(v));}
__device__ __forceinline__ u64 fma2(u64 a,u64 b,u64 c){u64 d;asm("fma.rn.f32x2 %0,%1,%2,%3;":"=l"(d):"l"(a),"l"(b),"l"(c));return d;}
__device__ __forceinline__ u64 mul2(u64 a,u64 b){u64 d;asm("mul.rn.f32x2 %0,%1,%2;":"=l"(d):"l"(a),"l"(b));return d;}

// ---------------------------------------------------------------------------
// prep1: 8-way s-split partials. COMPUTE index in q-plane layout (warp =
// consecutive cj, same q -> SMEM reads j-consecutive/broadcast, conflict-free;
// W_su fetched as 12 upfront float4 -> MLP 12). STORE in pair layout [cj*8+q]
// so consumers read two coalesced float4 per (c,j).
// ---------------------------------------------------------------------------
__global__ void prep1(const float* __restrict__ W_su, const float* __restrict__ W_out){
    __shared__ float Ws[CFRAME*NAA];
    for (int i = threadIdx.x; i < CFRAME*NAA; i += blockDim.x) Ws[i] = W_out[i];
    __syncthreads();
    int t = blockIdx.x*blockDim.x + threadIdx.x;
    if (t >= 8*CFRAME*NAA) return;
    int q  = t / (CFRAME*NAA);
    int cj = t - q*(CFRAME*NAA);
    int c = cj / NAA, j = cj - c*NAA;
    const float4* wr4 = (const float4*)(W_su + (size_t)c*CFRAME + q*48);
    float4 xv[12];
    #pragma unroll
    for (int k = 0; k < 12; k++) xv[k] = wr4[k];
    const float* wo = Ws + (size_t)(q*48)*NAA + j;
    float a0=0.f, a1=0.f, a2=0.f, a3=0.f;
    #pragma unroll
    for (int k = 0; k < 12; k++){
        a0 = fmaf(xv[k].x, wo[(k*4+0)*NAA], a0);
        a1 = fmaf(xv[k].y, wo[(k*4+1)*NAA], a1);
        a2 = fmaf(xv[k].z, wo[(k*4+2)*NAA], a2);
        a3 = fmaf(xv[k].w, wo[(k*4+3)*NAA], a3);
    }
    g_Wc8[(size_t)cj*8 + q] = (a0+a1) + (a2+a3);
}

// sum the 8 adjacent partials for (c,j): two coalesced float4 loads
__device__ __forceinline__ float wc_of(int c, int j){
    const float4* p = (const float4*)(g_Wc8 + (size_t)(c*NAA + j)*8);
    float4 a = p[0], b = p[1];
    return ((a.x+a.y)+(a.z+a.w)) + ((b.x+b.y)+(b.z+b.w));
}

// ---------------------------------------------------------------------------
// prep2: blocks 0-1 build tables (wc_of, parallel over 384 channels);
// block 2 reduces partials->SMEM then computes A/B in parallel + idx probe;
// blocks >= 3 zero the output buffer.
// ---------------------------------------------------------------------------
__global__ void prep2(const float* __restrict__ ln_g, const float* __restrict__ ln_b,
                      const float* __restrict__ b_su, const float* __restrict__ W_out,
                      const float* __restrict__ b_out, const void* __restrict__ idx_ptr,
                      float4* __restrict__ outz){
    if (blockIdx.x >= 3){
        int i = (blockIdx.x - 3)*blockDim.x + threadIdx.x;
        if (i < OUT_F4) outz[i] = make_float4(0.f, 0.f, 0.f, 0.f);
        return;
    }
    if (blockIdx.x < 2){
        int c = blockIdx.x*blockDim.x + threadIdx.x;   // active < 384
        if (c < CFRAME){
            float g = ln_g[c];
            float wc[NAA];
            #pragma unroll
            for (int j = 0; j < NAA; j++) wc[j] = wc_of(c, j);
            const float* wo = W_out + c*NAA;
            #pragma unroll
            for (int k = 0; k < 5; k++){
                g_Wg[c*6+k] = make_float4(g*wc[4*k], g*wc[4*k+1], g*wc[4*k+2], g*wc[4*k+3]);
                g_Wo[c*6+k] = make_float4(wo[4*k], wo[4*k+1], wo[4*k+2], wo[4*k+3]);
            }
            g_Wg[c*6+5] = make_float4(g*wc[20], 1.0f, 0.f, 0.f);   // ones col -> sum(x)
            g_Wo[c*6+5] = make_float4(wo[20],   0.0f, 0.f, 0.f);
        }
        return;
    }
    // block 2: reduce partials into SMEM, then parallel A/B vectors + probe
    __shared__ float swc[CFRAME*NAA];
    __shared__ float sA[NAA][8], sB[NAA][8];
    const int tid = threadIdx.x;
    for (int i = tid; i < CFRAME*NAA; i += blockDim.x){
        float4 a = ((const float4*)g_Wc8)[i*2];
        float4 b = ((const float4*)g_Wc8)[i*2+1];
        swc[i] = ((a.x+a.y)+(a.z+a.w)) + ((b.x+b.y)+(b.z+b.w));
    }
    __syncthreads();
    if (tid < NAA*8){
        const int j  = tid >> 3;
        const int ch = tid & 7;
        const int s0 = ch*48;
        float A0=0.f,A1=0.f, B0=0.f,B1=0.f, C0=0.f,C1=0.f;
        #pragma unroll 4
        for (int s = s0; s < s0+48; s += 2){
            float w0 = swc[(s+0)*NAA + j];
            float w1 = swc[(s+1)*NAA + j];
            A0 = fmaf(ln_g[s+0], w0, A0);  A1 = fmaf(ln_g[s+1], w1, A1);
            B0 = fmaf(ln_b[s+0], w0, B0);  B1 = fmaf(ln_b[s+1], w1, B1);
            C0 = fmaf(b_su[s+0], W_out[(s+0)*NAA+j], C0);
            C1 = fmaf(b_su[s+1], W_out[(s+1)*NAA+j], C1);
        }
        sA[j][ch] = A0 + A1;
        sB[j][ch] = (B0 + B1) + (C0 + C1);
    }
    __syncthreads();
    if (tid < NAA){
        int j = tid;
        float A = 0.f, Bv = 0.f;
        #pragma unroll
        for (int ch = 0; ch < 8; ch++){ A += sA[j][ch]; Bv += sB[j][ch]; }
        ((float*)g_A2)[j]  = A;
        ((float*)g_B2)[j]  = Bv;
        ((float*)g_Bo2)[j] = b_out[j];
        if (j == 20){ ((float*)g_A2)[21]=0.f; ((float*)g_B2)[21]=0.f; ((float*)g_Bo2)[21]=0.f; }
    } else if (tid >= 192 && tid < 224){
        // parallel idx dtype probe on a clean full warp
        int lane = tid - 192;
        const long long* p = (const long long*)idx_ptr;
        long long v0 = p[lane], v1 = p[lane + 32];
        bool ok = (v0 >= 0 && v0 < NRES) && (v1 >= 0 && v1 < NRES);
        unsigned b = __ballot_sync(0xffffffffu, ok);
        if (lane == 0) g_idx64 = (b == 0xffffffffu) ? 1 : 0;
    }
}

// ---------------------------------------------------------------------------
// per-row epilogues
// ---------------------------------------------------------------------------
__device__ __forceinline__ void epi_res(const u64 acc[11], float* __restrict__ out, int row){
    float* dst = out + (size_t)row*NAA;
    #pragma unroll
    for (int q = 0; q < 10; q++){
        float2 bo = g_Bo2[q];
        float o0, o1; upk2(acc[q], o0, o1);
        atomicAdd(dst + 2*q,     o0 + bo.x);
        atomicAdd(dst + 2*q + 1, o1 + bo.y);
    }
    float accS, dumm; upk2(acc[10], accS, dumm);
    atomicAdd(dst + 20, accS + g_Bo2[10].x);
}

__device__ __forceinline__ void epi_rigid(const u64 acc[11], float s2,
                                          const void* __restrict__ idxp,
                                          const float* __restrict__ mask,
                                          float* __restrict__ out, int row, int use64){
    float accS, s; upk2(acc[10], accS, s);
    const float mu = s * (1.f/CFRAME);
    const float rs = rsqrtf(fmaf(s2, 1.f/CFRAME, -mu*mu) + 1e-5f);
    const float m  = mask[row];
    const int iv = use64 ? (int)((const long long*)idxp)[row]
                         : ((const int*)idxp)[row];
    if (m != 0.f){
        float* dst = out + ((size_t)(row >> 13)*NRES + (size_t)iv)*NAA;
        const float rm = rs*m;
        const u64 rmd = dup2(rm), md = dup2(m), nmud = dup2(-mu);
        #pragma unroll
        for (int q = 0; q < 10; q++){
            float2 a = g_A2[q], b = g_B2[q];
            u64 o = fma2(nmud, pk2(a.x,a.y), acc[q]);      // acc - mu*A
            o     = fma2(rmd, o, mul2(md, pk2(b.x,b.y)));  // rs*m*(..) + m*B
            float o0, o1; upk2(o, o0, o1);
            atomicAdd(dst + 2*q,     o0);
            atomicAdd(dst + 2*q + 1, o1);
        }
        float oS = rm*(accS - mu*g_A2[10].x) + m*g_B2[10].x;
        atomicAdd(dst + 20, oS);
    }
}

// ---------------------------------------------------------------------------
// tile engine (R9/R11/R15 — best measured, UNCHANGED): 64-row tile, lane owns
// rows (lane, lane+32); 12 chunks x 32 channels; CH9 staging.
// ---------------------------------------------------------------------------
template<bool RES>
__device__ __forceinline__ void do_tile(int row0, const float* __restrict__ xbase,
                                        const float4* __restrict__ W,
                                        const void* __restrict__ idxp,
                                        const float* __restrict__ mask,
                                        float* __restrict__ out,
                                        float4* __restrict__ xs, int lane, int use64){
    u64 accA[11], accB[11];
    #pragma unroll
    for (int q = 0; q < 11; q++){ accA[q] = 0ull; accB[q] = 0ull; }
    float s2A = 0.f, s2B = 0.f;

    const int qld = lane & 7, sub = lane >> 3;

    for (int cb = 0; cb < 12; cb++){
        #pragma unroll
        for (int r = 0; r < 16; r++){
            int row = r*4 + sub;
            xs[row*CH9 + qld] =
                *(const float4*)(xbase + (size_t)(row0+row)*CFRAME + cb*32 + qld*4);
        }
        __syncwarp();
        #pragma unroll 2
        for (int i = 0; i < 8; i++){
            float4 xa = xs[lane*CH9 + i];
            float4 xb = xs[(lane+32)*CH9 + i];
            const float fa4[4] = {xa.x, xa.y, xa.z, xa.w};
            const float fb4[4] = {xb.x, xb.y, xb.z, xb.w};
            #pragma unroll
            for (int u = 0; u < 4; u++){
                const int c = cb*32 + i*4 + u;
                const float fa = fa4[u], fb = fb4[u];
                if (!RES){ s2A = fmaf(fa, fa, s2A); s2B = fmaf(fb, fb, s2B); }
                const u64 da = dup2(fa), db = dup2(fb);
                const float4* wc = W + c*6;
                float4 w0 = wc[0], w1 = wc[1], w2 = wc[2], w3 = wc[3], w4 = wc[4];
                float2 w5 = *(const float2*)(wc + 5);
                u64 p0 = pk2(w0.x,w0.y), p1 = pk2(w0.z,w0.w);
                u64 p2 = pk2(w1.x,w1.y), p3 = pk2(w1.z,w1.w);
                u64 p4 = pk2(w2.x,w2.y), p5 = pk2(w2.z,w2.w);
                u64 p6 = pk2(w3.x,w3.y), p7 = pk2(w3.z,w3.w);
                u64 p8 = pk2(w4.x,w4.y), p9 = pk2(w4.z,w4.w);
                u64 p10= pk2(w5.x,w5.y);
                accA[0] = fma2(da, p0, accA[0]);  accB[0] = fma2(db, p0, accB[0]);
                accA[1] = fma2(da, p1, accA[1]);  accB[1] = fma2(db, p1, accB[1]);
                accA[2] = fma2(da, p2, accA[2]);  accB[2] = fma2(db, p2, accB[2]);
                accA[3] = fma2(da, p3, accA[3]);  accB[3] = fma2(db, p3, accB[3]);
                accA[4] = fma2(da, p4, accA[4]);  accB[4] = fma2(db, p4, accB[4]);
                accA[5] = fma2(da, p5, accA[5]);  accB[5] = fma2(db, p5, accB[5]);
                accA[6] = fma2(da, p6, accA[6]);  accB[6] = fma2(db, p6, accB[6]);
                accA[7] = fma2(da, p7, accA[7]);  accB[7] = fma2(db, p7, accB[7]);
                accA[8] = fma2(da, p8, accA[8]);  accB[8] = fma2(db, p8, accB[8]);
                accA[9] = fma2(da, p9, accA[9]);  accB[9] = fma2(db, p9, accB[9]);
                accA[10]= fma2(da, p10, accA[10]);accB[10]= fma2(db, p10, accB[10]);
            }
        }
        __syncwarp();
    }

    if (RES){
        epi_res(accA, out, row0 + lane);
        epi_res(accB, out, row0 + lane + 32);
    } else {
        epi_rigid(accA, s2A, idxp, mask, out, row0 + lane,      use64);
        epi_rigid(accB, s2B, idxp, mask, out, row0 + lane + 32, use64);
    }
}

// ---------------------------------------------------------------------------
// fused kernel (R9/R11/R15 — best measured, UNCHANGED): unified tile space,
// static grid-stride; both weight tables resident in SMEM.
// ---------------------------------------------------------------------------
__global__ void __launch_bounds__(THREADS,2)
fused_kernel(const float* __restrict__ x, const void* __restrict__ idxp,
             const float* __restrict__ mask, const float* __restrict__ seqo,
             float* __restrict__ out){
    extern __shared__ float4 sm4[];
    float4* Wg = sm4;                 // WTAB
    float4* Wo = sm4 + WTAB;          // WTAB
    const int lane = threadIdx.x & 31;
    const int w    = threadIdx.x >> 5;
    float4* xs = sm4 + 2*WTAB + w*STAGE_F4;

    for (int i = threadIdx.x; i < WTAB; i += THREADS){
        Wg[i] = g_Wg[i];
        Wo[i] = g_Wo[i];
    }
    __syncthreads();
    const int use64 = g_idx64;

    const int gw = blockIdx.x*4 + w;
    for (int t = gw; t < NTILES; t += WARPS_TOTAL){
        if (t < RIGID_TILES)
            do_tile<false>(t*TILE_ROWS, x, Wg, idxp, mask, out, xs, lane, use64);
        else
            do_tile<true>((t-RIGID_TILES)*TILE_ROWS, seqo, Wo, idxp, mask, out, xs, lane, use64);
    }
}

// ---------------------------------------------------------------------------
extern "C" void kernel_launch(void* const* d_in, const int* in_sizes, int n_in,
                              void* d_out, int out_size) {
    const float* x     = (const float*)d_in[0];  // rigids_embed_flat [16,8192,384]
    const void*  idxp  = d_in[1];                // rigids_to_res_idx [16,8192]
    const float* mask  = (const float*)d_in[2];  // rigids_mask [16,8192]
    const float* seqo  = (const float*)d_in[3];  // out [16,2048,384]
    const float* ln_g  = (const float*)d_in[4];
    const float* ln_b  = (const float*)d_in[5];
    const float* W_su  = (const float*)d_in[6];  // [384,384]
    const float* b_su  = (const float*)d_in[7];  // [384]
    const float* W_out = (const float*)d_in[8];  // [384,21]
    const float* b_out = (const float*)d_in[9];  // [21]
    float* out = (float*)d_out;                  // [16,2048,21]

    cudaFuncSetAttribute(fused_kernel,
                         cudaFuncAttributeMaxDynamicSharedMemorySize, SMEM_BYTES);

    prep1<<<(8*CFRAME*NAA + 255)/256, 256>>>(W_su, W_out);
    prep2<<<3 + (OUT_F4 + 255)/256, 256>>>(ln_g, ln_b, b_su, W_out, b_out, idxp,
                                           (float4*)out);
    fused_kernel<<<NBLOCKS, THREADS, SMEM_BYTES>>>(x, idxp, mask, seqo, out);
}

// round 17
// speedup vs baseline: 1.5638x; 1.0158x over previous
#include <cuda_runtime.h>

#define CFRAME 384
#define NAA    21
#define NRES   2048
#define NRIG   8192
#define BATCH  16
#define THREADS 128                     // 4 warps per block
#define NBLOCKS 296                     // 2 blocks/SM (smem-capped)
#define WARPS_TOTAL (NBLOCKS*4)         // 1184
#define TILE_ROWS 64
#define RIGID_TILES ((BATCH*NRIG)/TILE_ROWS)   // 2048
#define RES_TILES   ((BATCH*NRES)/TILE_ROWS)   // 512
#define NTILES (RIGID_TILES + RES_TILES)       // 2560
#define WTAB   (CFRAME*6)               // float4 per weight table (2304)
#define CH9    9                        // stage row stride in float4 (8 used + 1 pad)
#define STAGE_F4 (TILE_ROWS*CH9)        // 576 float4 per warp
#define SMEM_F4 (2*WTAB + 4*STAGE_F4)   // 6912 float4
#define SMEM_BYTES (SMEM_F4*16)         // 110592
#define OUT_F4 ((BATCH*NRES*NAA)/4)     // 172032 float4 (exact)
#define P1_COMPUTE_BLOCKS ((8*CFRAME*NAA + 255)/256)   // 252
#define P1_ZERO_BLOCKS    ((OUT_F4 + 255)/256)         // 672

typedef unsigned long long u64;

// ---------------- device scratch (no allocations) ---------------------------
__device__ float4 g_Wg[WTAB];    // rigid: g-folded Wc; [c*6+5] = (g*wc20, 1, 0, 0)
__device__ float4 g_Wo[WTAB];    // res:   W_out;       [c*6+5] = (w20, 0, 0, 0)
__device__ float2 g_A2[11];
__device__ float2 g_B2[11];
__device__ float2 g_Bo2[11];
__device__ float  g_Wc8[8*CFRAME*NAA];  // 8 s-partials of Wc, PAIR layout [cj*8 + q]
__device__ int    g_idx64;

// ---- packed f32x2 helpers ----
__device__ __forceinline__ u64 pk2(float lo, float hi){u64 r;asm("mov.b64 %0,{%1,%2};":"=l"(r):"f"(lo),"f"(hi));return r;}
__device__ __forceinline__ u64 dup2(float v){return pk2(v,v);}
__device__ __forceinline__ void upk2(u64 v,float&lo,float&hi){asm("mov.b64 {%0,%1},%2;":"=f"(lo),"=f"(hi):"l"(v));}
__device__ __forceinline__ u64 fma2(u64 a,u64 b,u64 c){u64 d;asm("fma.rn.f32x2 %0,%1,%2,%3;":"=l"(d):"l"(a),"l"(b),"l"(c));return d;}
__device__ __forceinline__ u64 mul2(u64 a,u64 b){u64 d;asm("mul.rn.f32x2 %0,%1,%2;":"=l"(d):"l"(a),"l"(b));return d;}

// ---------------------------------------------------------------------------
// prep1: compute blocks [0,252) produce 8-way s-split partials reading W_out
// directly (warp-coalesced, L1/L2-resident; no staging, no barrier).
// Blocks >= 252 zero the output buffer in parallel.
// ---------------------------------------------------------------------------
__global__ void prep1(const float* __restrict__ W_su, const float* __restrict__ W_out,
                      float4* __restrict__ outz){
    if (blockIdx.x >= P1_COMPUTE_BLOCKS){
        int i = (blockIdx.x - P1_COMPUTE_BLOCKS)*blockDim.x + threadIdx.x;
        if (i < OUT_F4) outz[i] = make_float4(0.f, 0.f, 0.f, 0.f);
        return;
    }
    int t = blockIdx.x*blockDim.x + threadIdx.x;
    if (t >= 8*CFRAME*NAA) return;
    int q  = t / (CFRAME*NAA);
    int cj = t - q*(CFRAME*NAA);
    int c = cj / NAA, j = cj - c*NAA;
    const float4* wr4 = (const float4*)(W_su + (size_t)c*CFRAME + q*48);
    float4 xv[12];
    #pragma unroll
    for (int k = 0; k < 12; k++) xv[k] = wr4[k];
    const float* wo = W_out + (size_t)(q*48)*NAA + j;
    float a0=0.f, a1=0.f, a2=0.f, a3=0.f;
    #pragma unroll
    for (int k = 0; k < 12; k++){
        a0 = fmaf(xv[k].x, __ldg(wo + (k*4+0)*NAA), a0);
        a1 = fmaf(xv[k].y, __ldg(wo + (k*4+1)*NAA), a1);
        a2 = fmaf(xv[k].z, __ldg(wo + (k*4+2)*NAA), a2);
        a3 = fmaf(xv[k].w, __ldg(wo + (k*4+3)*NAA), a3);
    }
    g_Wc8[(size_t)cj*8 + q] = (a0+a1) + (a2+a3);
}

// sum the 8 adjacent partials for (c,j): two coalesced float4 loads
__device__ __forceinline__ float wc_of(int c, int j){
    const float4* p = (const float4*)(g_Wc8 + (size_t)(c*NAA + j)*8);
    float4 a = p[0], b = p[1];
    return ((a.x+a.y)+(a.z+a.w)) + ((b.x+b.y)+(b.z+b.w));
}

// ---------------------------------------------------------------------------
// prep2 (3 blocks): blocks 0-1 build tables (wc_of, parallel over channels);
// block 2 reduces partials->SMEM then computes A/B in parallel + idx probe.
// ---------------------------------------------------------------------------
__global__ void prep2(const float* __restrict__ ln_g, const float* __restrict__ ln_b,
                      const float* __restrict__ b_su, const float* __restrict__ W_out,
                      const float* __restrict__ b_out, const void* __restrict__ idx_ptr){
    if (blockIdx.x < 2){
        int c = blockIdx.x*blockDim.x + threadIdx.x;   // active < 384
        if (c < CFRAME){
            float g = ln_g[c];
            float wc[NAA];
            #pragma unroll
            for (int j = 0; j < NAA; j++) wc[j] = wc_of(c, j);
            const float* wo = W_out + c*NAA;
            #pragma unroll
            for (int k = 0; k < 5; k++){
                g_Wg[c*6+k] = make_float4(g*wc[4*k], g*wc[4*k+1], g*wc[4*k+2], g*wc[4*k+3]);
                g_Wo[c*6+k] = make_float4(wo[4*k], wo[4*k+1], wo[4*k+2], wo[4*k+3]);
            }
            g_Wg[c*6+5] = make_float4(g*wc[20], 1.0f, 0.f, 0.f);   // ones col -> sum(x)
            g_Wo[c*6+5] = make_float4(wo[20],   0.0f, 0.f, 0.f);
        }
        return;
    }
    // block 2: reduce partials into SMEM, then parallel A/B vectors + probe
    __shared__ float swc[CFRAME*NAA];
    __shared__ float sA[NAA][8], sB[NAA][8];
    const int tid = threadIdx.x;
    for (int i = tid; i < CFRAME*NAA; i += blockDim.x){
        float4 a = ((const float4*)g_Wc8)[i*2];
        float4 b = ((const float4*)g_Wc8)[i*2+1];
        swc[i] = ((a.x+a.y)+(a.z+a.w)) + ((b.x+b.y)+(b.z+b.w));
    }
    __syncthreads();
    if (tid < NAA*8){
        const int j  = tid >> 3;
        const int ch = tid & 7;
        const int s0 = ch*48;
        float A0=0.f,A1=0.f, B0=0.f,B1=0.f, C0=0.f,C1=0.f;
        #pragma unroll 4
        for (int s = s0; s < s0+48; s += 2){
            float w0 = swc[(s+0)*NAA + j];
            float w1 = swc[(s+1)*NAA + j];
            A0 = fmaf(ln_g[s+0], w0, A0);  A1 = fmaf(ln_g[s+1], w1, A1);
            B0 = fmaf(ln_b[s+0], w0, B0);  B1 = fmaf(ln_b[s+1], w1, B1);
            C0 = fmaf(b_su[s+0], W_out[(s+0)*NAA+j], C0);
            C1 = fmaf(b_su[s+1], W_out[(s+1)*NAA+j], C1);
        }
        sA[j][ch] = A0 + A1;
        sB[j][ch] = (B0 + B1) + (C0 + C1);
    }
    __syncthreads();
    if (tid < NAA){
        int j = tid;
        float A = 0.f, Bv = 0.f;
        #pragma unroll
        for (int ch = 0; ch < 8; ch++){ A += sA[j][ch]; Bv += sB[j][ch]; }
        ((float*)g_A2)[j]  = A;
        ((float*)g_B2)[j]  = Bv;
        ((float*)g_Bo2)[j] = b_out[j];
        if (j == 20){ ((float*)g_A2)[21]=0.f; ((float*)g_B2)[21]=0.f; ((float*)g_Bo2)[21]=0.f; }
    } else if (tid >= 192 && tid < 224){
        // parallel idx dtype probe on a clean full warp
        int lane = tid - 192;
        const long long* p = (const long long*)idx_ptr;
        long long v0 = p[lane], v1 = p[lane + 32];
        bool ok = (v0 >= 0 && v0 < NRES) && (v1 >= 0 && v1 < NRES);
        unsigned b = __ballot_sync(0xffffffffu, ok);
        if (lane == 0) g_idx64 = (b == 0xffffffffu) ? 1 : 0;
    }
}

// ---------------------------------------------------------------------------
// per-row epilogues
// ---------------------------------------------------------------------------
__device__ __forceinline__ void epi_res(const u64 acc[11], float* __restrict__ out, int row){
    float* dst = out + (size_t)row*NAA;
    #pragma unroll
    for (int q = 0; q < 10; q++){
        float2 bo = g_Bo2[q];
        float o0, o1; upk2(acc[q], o0, o1);
        atomicAdd(dst + 2*q,     o0 + bo.x);
        atomicAdd(dst + 2*q + 1, o1 + bo.y);
    }
    float accS, dumm; upk2(acc[10], accS, dumm);
    atomicAdd(dst + 20, accS + g_Bo2[10].x);
}

__device__ __forceinline__ void epi_rigid(const u64 acc[11], float s2,
                                          const void* __restrict__ idxp,
                                          const float* __restrict__ mask,
                                          float* __restrict__ out, int row, int use64){
    float accS, s; upk2(acc[10], accS, s);
    const float mu = s * (1.f/CFRAME);
    const float rs = rsqrtf(fmaf(s2, 1.f/CFRAME, -mu*mu) + 1e-5f);
    const float m  = mask[row];
    const int iv = use64 ? (int)((const long long*)idxp)[row]
                         : ((const int*)idxp)[row];
    if (m != 0.f){
        float* dst = out + ((size_t)(row >> 13)*NRES + (size_t)iv)*NAA;
        const float rm = rs*m;
        const u64 rmd = dup2(rm), md = dup2(m), nmud = dup2(-mu);
        #pragma unroll
        for (int q = 0; q < 10; q++){
            float2 a = g_A2[q], b = g_B2[q];
            u64 o = fma2(nmud, pk2(a.x,a.y), acc[q]);      // acc - mu*A
            o     = fma2(rmd, o, mul2(md, pk2(b.x,b.y)));  // rs*m*(..) + m*B
            float o0, o1; upk2(o, o0, o1);
            atomicAdd(dst + 2*q,     o0);
            atomicAdd(dst + 2*q + 1, o1);
        }
        float oS = rm*(accS - mu*g_A2[10].x) + m*g_B2[10].x;
        atomicAdd(dst + 20, oS);
    }
}

// ---------------------------------------------------------------------------
// tile engine (R9/R11/R15/R16 — best measured, UNCHANGED): 64-row tile, lane
// owns rows (lane, lane+32); 12 chunks x 32 channels; CH9 staging.
// ---------------------------------------------------------------------------
template<bool RES>
__device__ __forceinline__ void do_tile(int row0, const float* __restrict__ xbase,
                                        const float4* __restrict__ W,
                                        const void* __restrict__ idxp,
                                        const float* __restrict__ mask,
                                        float* __restrict__ out,
                                        float4* __restrict__ xs, int lane, int use64){
    u64 accA[11], accB[11];
    #pragma unroll
    for (int q = 0; q < 11; q++){ accA[q] = 0ull; accB[q] = 0ull; }
    float s2A = 0.f, s2B = 0.f;

    const int qld = lane & 7, sub = lane >> 3;

    for (int cb = 0; cb < 12; cb++){
        #pragma unroll
        for (int r = 0; r < 16; r++){
            int row = r*4 + sub;
            xs[row*CH9 + qld] =
                *(const float4*)(xbase + (size_t)(row0+row)*CFRAME + cb*32 + qld*4);
        }
        __syncwarp();
        #pragma unroll 2
        for (int i = 0; i < 8; i++){
            float4 xa = xs[lane*CH9 + i];
            float4 xb = xs[(lane+32)*CH9 + i];
            const float fa4[4] = {xa.x, xa.y, xa.z, xa.w};
            const float fb4[4] = {xb.x, xb.y, xb.z, xb.w};
            #pragma unroll
            for (int u = 0; u < 4; u++){
                const int c = cb*32 + i*4 + u;
                const float fa = fa4[u], fb = fb4[u];
                if (!RES){ s2A = fmaf(fa, fa, s2A); s2B = fmaf(fb, fb, s2B); }
                const u64 da = dup2(fa), db = dup2(fb);
                const float4* wc = W + c*6;
                float4 w0 = wc[0], w1 = wc[1], w2 = wc[2], w3 = wc[3], w4 = wc[4];
                float2 w5 = *(const float2*)(wc + 5);
                u64 p0 = pk2(w0.x,w0.y), p1 = pk2(w0.z,w0.w);
                u64 p2 = pk2(w1.x,w1.y), p3 = pk2(w1.z,w1.w);
                u64 p4 = pk2(w2.x,w2.y), p5 = pk2(w2.z,w2.w);
                u64 p6 = pk2(w3.x,w3.y), p7 = pk2(w3.z,w3.w);
                u64 p8 = pk2(w4.x,w4.y), p9 = pk2(w4.z,w4.w);
                u64 p10= pk2(w5.x,w5.y);
                accA[0] = fma2(da, p0, accA[0]);  accB[0] = fma2(db, p0, accB[0]);
                accA[1] = fma2(da, p1, accA[1]);  accB[1] = fma2(db, p1, accB[1]);
                accA[2] = fma2(da, p2, accA[2]);  accB[2] = fma2(db, p2, accB[2]);
                accA[3] = fma2(da, p3, accA[3]);  accB[3] = fma2(db, p3, accB[3]);
                accA[4] = fma2(da, p4, accA[4]);  accB[4] = fma2(db, p4, accB[4]);
                accA[5] = fma2(da, p5, accA[5]);  accB[5] = fma2(db, p5, accB[5]);
                accA[6] = fma2(da, p6, accA[6]);  accB[6] = fma2(db, p6, accB[6]);
                accA[7] = fma2(da, p7, accA[7]);  accB[7] = fma2(db, p7, accB[7]);
                accA[8] = fma2(da, p8, accA[8]);  accB[8] = fma2(db, p8, accB[8]);
                accA[9] = fma2(da, p9, accA[9]);  accB[9] = fma2(db, p9, accB[9]);
                accA[10]= fma2(da, p10, accA[10]);accB[10]= fma2(db, p10, accB[10]);
            }
        }
        __syncwarp();
    }

    if (RES){
        epi_res(accA, out, row0 + lane);
        epi_res(accB, out, row0 + lane + 32);
    } else {
        epi_rigid(accA, s2A, idxp, mask, out, row0 + lane,      use64);
        epi_rigid(accB, s2B, idxp, mask, out, row0 + lane + 32, use64);
    }
}

// ---------------------------------------------------------------------------
// fused kernel (best measured, UNCHANGED): unified tile space, static
// grid-stride; both weight tables resident in SMEM.
// ---------------------------------------------------------------------------
__global__ void __launch_bounds__(THREADS,2)
fused_kernel(const float* __restrict__ x, const void* __restrict__ idxp,
             const float* __restrict__ mask, const float* __restrict__ seqo,
             float* __restrict__ out){
    extern __shared__ float4 sm4[];
    float4* Wg = sm4;                 // WTAB
    float4* Wo = sm4 + WTAB;          // WTAB
    const int lane = threadIdx.x & 31;
    const int w    = threadIdx.x >> 5;
    float4* xs = sm4 + 2*WTAB + w*STAGE_F4;

    for (int i = threadIdx.x; i < WTAB; i += THREADS){
        Wg[i] = g_Wg[i];
        Wo[i] = g_Wo[i];
    }
    __syncthreads();
    const int use64 = g_idx64;

    const int gw = blockIdx.x*4 + w;
    for (int t = gw; t < NTILES; t += WARPS_TOTAL){
        if (t < RIGID_TILES)
            do_tile<false>(t*TILE_ROWS, x, Wg, idxp, mask, out, xs, lane, use64);
        else
            do_tile<true>((t-RIGID_TILES)*TILE_ROWS, seqo, Wo, idxp, mask, out, xs, lane, use64);
    }
}

// ---------------------------------------------------------------------------
extern "C" void kernel_launch(void* const* d_in, const int* in_sizes, int n_in,
                              void* d_out, int out_size) {
    const float* x     = (const float*)d_in[0];  // rigids_embed_flat [16,8192,384]
    const void*  idxp  = d_in[1];                // rigids_to_res_idx [16,8192]
    const float* mask  = (const float*)d_in[2];  // rigids_mask [16,8192]
    const float* seqo  = (const float*)d_in[3];  // out [16,2048,384]
    const float* ln_g  = (const float*)d_in[4];
    const float* ln_b  = (const float*)d_in[5];
    const float* W_su  = (const float*)d_in[6];  // [384,384]
    const float* b_su  = (const float*)d_in[7];  // [384]
    const float* W_out = (const float*)d_in[8];  // [384,21]
    const float* b_out = (const float*)d_in[9];  // [21]
    float* out = (float*)d_out;                  // [16,2048,21]

    cudaFuncSetAttribute(fused_kernel,
                         cudaFuncAttributeMaxDynamicSharedMemorySize, SMEM_BYTES);

    prep1<<<P1_COMPUTE_BLOCKS + P1_ZERO_BLOCKS, 256>>>(W_su, W_out, (float4*)out);
    prep2<<<3, 256>>>(ln_g, ln_b, b_su, W_out, b_out, idxp);
    fused_kernel<<<NBLOCKS, THREADS, SMEM_BYTES>>>(x, idxp, mask, seqo, out);
}